// round 7
// baseline (speedup 1.0000x reference)
#include <cuda_runtime.h>
#include <float.h>

#define NUM_SEQS 64
#define NUM_HEADS 32
#define NUM_KV_HEADS 8
#define HEAD_SIZE 128
#define BLOCK_SIZE 16
#define MAX_BLOCKS_PER_SEQ 64
#define Q_PER_KV 4
#define ATTN_SCALE 0.08838834764831845f

#define NWARPS 8
#define SPLITS 4
#define BLOCKS_PER_SPLIT 16      // contiguous: split s owns blocks [16s, 16s+16)

__device__ float g_acc[NUM_SEQS][NUM_KV_HEADS][SPLITS][Q_PER_KV][HEAD_SIZE];
__device__ float g_ml [NUM_SEQS][NUM_KV_HEADS][SPLITS][Q_PER_KV][2];
__device__ unsigned int g_cnt[NUM_SEQS][NUM_KV_HEADS];   // zero-init; self-resetting

__global__ __launch_bounds__(256, 3)
void paged_attn_fused(const float* __restrict__ query,
                      const float* __restrict__ key_cache,
                      const float* __restrict__ value_cache,
                      const int*   __restrict__ block_tables,
                      const int*   __restrict__ context_lens,
                      float*       __restrict__ out)
{
    const int kvh   = blockIdx.x;
    const int seq   = blockIdx.y;
    const int split = blockIdx.z;
    const int tid   = threadIdx.x;
    const int warp  = tid >> 5;
    const int lane  = tid & 31;

    const int ctx     = context_lens[seq];
    const int nblocks = (ctx + BLOCK_SIZE - 1) / BLOCK_SIZE;
    if (split * BLOCKS_PER_SPLIT >= nblocks) return;
    const int nsplits = (nblocks + BLOCKS_PER_SPLIT - 1) / BLOCKS_PER_SPLIT;

    __shared__ float q_s[Q_PER_KV * HEAD_SIZE];
    __shared__ float w_m[NWARPS][Q_PER_KV];
    __shared__ float w_l[NWARPS][Q_PER_KV];
    __shared__ float w_acc[NWARPS][Q_PER_KV][HEAD_SIZE];
    __shared__ float mg_s[Q_PER_KV];
    __shared__ float den_s[Q_PER_KV];
    __shared__ float f_s[NWARPS][Q_PER_KV];
    __shared__ int   last_s;

    for (int i = tid; i < Q_PER_KV * HEAD_SIZE; i += 256)
        q_s[i] = query[(size_t)(seq * NUM_HEADS + kvh * Q_PER_KV) * HEAD_SIZE + i] * ATTN_SCALE;
    __syncthreads();

    const int blk0 = split * BLOCKS_PER_SPLIT + warp * 2;
    const int blk1 = blk0 + 1;
    const bool have0 = blk0 < nblocks;
    const bool have1 = blk1 < nblocks;

    if (have0) {
        const int pb0 = block_tables[seq * MAX_BLOCKS_PER_SEQ + blk0];
        const int pb1 = have1 ? block_tables[seq * MAX_BLOCKS_PER_SEQ + blk1] : pb0;
        const size_t base0 = ((size_t)pb0 * NUM_KV_HEADS + kvh) * 2048;
        const size_t base1 = ((size_t)pb1 * NUM_KV_HEADS + kvh) * 2048;

        // prefetch both V tiles to L2 while the K phase runs
        {
            const char* v0 = (const char*)(value_cache + base0);
            const char* v1 = (const char*)(value_cache + base1);
            asm volatile("prefetch.global.L2 [%0];" :: "l"(v0 + lane * 128));
            asm volatile("prefetch.global.L2 [%0];" :: "l"(v0 + 4096 + lane * 128));
            asm volatile("prefetch.global.L2 [%0];" :: "l"(v1 + lane * 128));
            asm volatile("prefetch.global.L2 [%0];" :: "l"(v1 + 4096 + lane * 128));
        }

        const int t_lane = lane >> 1;          // token 0..15
        const int dl0    = (lane & 1) * 4;     // 4-dim sub-slot in each 8-dim group

        // ---- K: fully coalesced; 4 segments of 8 LDG.128 (32 regs live, not 64)
        const float4* kb0 = (const float4*)(key_cache + base0);
        const float4* kb1 = (const float4*)(key_cache + base1);

        float s0[Q_PER_KV] = {0.f, 0.f, 0.f, 0.f};
        float s1[Q_PER_KV] = {0.f, 0.f, 0.f, 0.f};

        #pragma unroll
        for (int seg = 0; seg < 4; seg++) {
            const int b     = seg >> 1;
            const int batch = seg & 1;
            const float4* kbp = b ? kb1 : kb0;
            float4 kr[8];
            #pragma unroll
            for (int i = 0; i < 8; i++)
                kr[i] = kbp[(batch * 8 + i) * 32 + lane];
            #pragma unroll
            for (int i = 0; i < 8; i++) {
                const int j = batch * 8 + i;
                #pragma unroll
                for (int h = 0; h < Q_PER_KV; h++) {
                    const float4 q4 = *(const float4*)(q_s + h * HEAD_SIZE + j * 8 + dl0);
                    const float d = q4.x * kr[i].x + q4.y * kr[i].y
                                  + q4.z * kr[i].z + q4.w * kr[i].w;
                    if (b == 0) s0[h] += d; else s1[h] += d;
                }
            }
        }
        #pragma unroll
        for (int h = 0; h < Q_PER_KV; h++) {
            s0[h] += __shfl_xor_sync(0xffffffffu, s0[h], 1);
            s1[h] += __shfl_xor_sync(0xffffffffu, s1[h], 1);
        }

        const bool valid0 = (blk0 * BLOCK_SIZE + t_lane) < ctx;
        const bool valid1 = have1 && ((blk1 * BLOCK_SIZE + t_lane) < ctx);
        #pragma unroll
        for (int h = 0; h < Q_PER_KV; h++) {
            s0[h] = valid0 ? s0[h] : -1e30f;
            s1[h] = valid1 ? s1[h] : -1e30f;
        }

        // ---- joint softmax over the 32 tokens of both blocks
        float p0[Q_PER_KV], p1[Q_PER_KV];
        #pragma unroll
        for (int h = 0; h < Q_PER_KV; h++) {
            float bm = fmaxf(s0[h], s1[h]);
            #pragma unroll
            for (int off = 2; off < 32; off <<= 1)
                bm = fmaxf(bm, __shfl_xor_sync(0xffffffffu, bm, off));
            p0[h] = __expf(s0[h] - bm);
            p1[h] = __expf(s1[h] - bm);
            float ps = p0[h] + p1[h];
            #pragma unroll
            for (int off = 2; off < 32; off <<= 1)
                ps += __shfl_xor_sync(0xffffffffu, ps, off);
            if (lane == 0) { w_m[warp][h] = bm; w_l[warp][h] = ps; }
        }

        // ---- probs for this lane's 4 tokens (per block)
        float pt0[Q_PER_KV][4], pt1[Q_PER_KV][4];
        const int tok0 = (lane & 3) * 4;
        #pragma unroll
        for (int h = 0; h < Q_PER_KV; h++)
            #pragma unroll
            for (int j = 0; j < 4; j++) {
                pt0[h][j] = __shfl_sync(0xffffffffu, p0[h], (tok0 + j) * 2);
                pt1[h][j] = __shfl_sync(0xffffffffu, p1[h], (tok0 + j) * 2);
            }

        // ---- V: coalesced; lane = (dim 8k + lane/4, tokens tok0..tok0+3)
        const float4* vb0 = (const float4*)(value_cache + base0);
        const float4* vb1 = (const float4*)(value_cache + base1);
        const int dsub = lane >> 2;
        const int gsel = lane & 3;

        #pragma unroll
        for (int kk = 0; kk < 2; kk++) {
            float accv[Q_PER_KV][8];
            #pragma unroll
            for (int j = 0; j < 8; j++) {
                const int k = kk * 8 + j;
                const float4 v0 = vb0[k * 32 + lane];
                const float4 v1 = vb1[k * 32 + lane];
                #pragma unroll
                for (int h = 0; h < Q_PER_KV; h++)
                    accv[h][j] = v0.x * pt0[h][0] + v0.y * pt0[h][1]
                               + v0.z * pt0[h][2] + v0.w * pt0[h][3]
                               + v1.x * pt1[h][0] + v1.y * pt1[h][1]
                               + v1.z * pt1[h][2] + v1.w * pt1[h][3];
            }
            #pragma unroll
            for (int h = 0; h < Q_PER_KV; h++) {
                #pragma unroll
                for (int j = 0; j < 8; j++) {
                    float v = accv[h][j];
                    v += __shfl_xor_sync(0xffffffffu, v, 1);
                    v += __shfl_xor_sync(0xffffffffu, v, 2);
                    if (gsel == 0)
                        w_acc[warp][h][(kk * 8 + j) * 8 + dsub] = v;
                }
            }
        }
    } else {
        if (lane == 0) {
            #pragma unroll
            for (int h = 0; h < Q_PER_KV; h++) { w_m[warp][h] = -1e30f; w_l[warp][h] = 0.f; }
        }
        const float4 z = make_float4(0.f, 0.f, 0.f, 0.f);
        float4* wa = (float4*)w_acc[warp];     // 128 float4
        #pragma unroll
        for (int r = 0; r < 4; r++) wa[lane + r * 32] = z;
    }
    __syncthreads();

    // ---- CTA merge: per-warp scale factors
    if (tid < Q_PER_KV) {
        float mg = -1e30f;
        #pragma unroll
        for (int w = 0; w < NWARPS; w++) mg = fmaxf(mg, w_m[w][tid]);
        mg_s[tid] = mg;
    }
    __syncthreads();
    if (tid < NWARPS * Q_PER_KV) {
        const int w = tid >> 2;
        const int h = tid & 3;
        f_s[w][h] = __expf(w_m[w][h] - mg_s[h]);
    }
    __syncthreads();
    if (tid < Q_PER_KV) {
        float den = 0.f;
        #pragma unroll
        for (int w = 0; w < NWARPS; w++) den += w_l[w][tid] * f_s[w][tid];
        den_s[tid] = den;
    }
    __syncthreads();

    if (nsplits == 1) {
        // ---- fast path: only split -> write output directly, no scratch/atomic
        for (int o = tid; o < Q_PER_KV * HEAD_SIZE; o += 256) {
            const int h = o >> 7;
            const int d = o & 127;
            float num = 0.f;
            #pragma unroll
            for (int w = 0; w < NWARPS; w++) num += w_acc[w][h][d] * f_s[w][h];
            out[(size_t)(seq * NUM_HEADS + kvh * Q_PER_KV + h) * HEAD_SIZE + d] = num / den_s[h];
        }
        return;
    }

    if (tid < Q_PER_KV) {
        g_ml[seq][kvh][split][tid][0] = mg_s[tid];
        g_ml[seq][kvh][split][tid][1] = den_s[tid];
    }
    for (int o = tid; o < Q_PER_KV * HEAD_SIZE; o += 256) {
        const int h = o >> 7;
        const int d = o & 127;
        float num = 0.f;
        #pragma unroll
        for (int w = 0; w < NWARPS; w++) num += w_acc[w][h][d] * f_s[w][h];
        g_acc[seq][kvh][split][h][d] = num;
    }

    // ---- fused split merge: last-arriving CTA for this (seq,kvh) reduces
    __threadfence();
    __syncthreads();
    if (tid == 0) {
        const unsigned int old = atomicAdd(&g_cnt[seq][kvh], 1u);
        last_s = (old == (unsigned int)(nsplits - 1));
        if (last_s) g_cnt[seq][kvh] = 0u;   // self-reset for next graph replay
    }
    __syncthreads();
    if (!last_s) return;

    for (int o = tid; o < Q_PER_KV * HEAD_SIZE; o += 256) {
        const int h = o >> 7;
        const int d = o & 127;
        float gm = -1e30f;
        #pragma unroll
        for (int s = 0; s < SPLITS; s++)
            if (s < nsplits) gm = fmaxf(gm, g_ml[seq][kvh][s][h][0]);
        float num = 0.f, den = 0.f;
        #pragma unroll
        for (int s = 0; s < SPLITS; s++) {
            if (s < nsplits) {
                const float f = __expf(g_ml[seq][kvh][s][h][0] - gm);
                num += g_acc[seq][kvh][s][h][d] * f;
                den += g_ml[seq][kvh][s][h][1] * f;
            }
        }
        out[(size_t)(seq * NUM_HEADS + kvh * Q_PER_KV + h) * HEAD_SIZE + d] = num / den;
    }
}

extern "C" void kernel_launch(void* const* d_in, const int* in_sizes, int n_in,
                              void* d_out, int out_size)
{
    const float* query       = (const float*)d_in[0];
    const float* key_cache   = (const float*)d_in[1];
    const float* value_cache = (const float*)d_in[2];
    const int*   block_tables  = (const int*)d_in[3];
    const int*   context_lens  = (const int*)d_in[4];
    float* out = (float*)d_out;

    dim3 grid(NUM_KV_HEADS, NUM_SEQS, SPLITS);
    paged_attn_fused<<<grid, 256>>>(query, key_cache, value_cache,
                                    block_tables, context_lens, out);
}

// round 8
// speedup vs baseline: 1.7494x; 1.7494x over previous
#include <cuda_runtime.h>
#include <float.h>

#define NUM_SEQS 64
#define NUM_HEADS 32
#define NUM_KV_HEADS 8
#define HEAD_SIZE 128
#define BLOCK_SIZE 16
#define MAX_BLOCKS_PER_SEQ 64
#define Q_PER_KV 4
#define ATTN_SCALE 0.08838834764831845f

#define NWARPS 8
#define SPLITS 4
#define BLOCKS_PER_SPLIT 16   // activation granularity (CTA count identical to best kernel)

__device__ float g_acc[NUM_SEQS][NUM_KV_HEADS][SPLITS][Q_PER_KV][HEAD_SIZE];
__device__ float g_ml [NUM_SEQS][NUM_KV_HEADS][SPLITS][Q_PER_KV][2];
__device__ unsigned int g_cnt[NUM_SEQS][NUM_KV_HEADS];   // zero-init; self-resetting

__global__ __launch_bounds__(256, 2)
void paged_attn_fused(const float* __restrict__ query,
                      const float* __restrict__ key_cache,
                      const float* __restrict__ value_cache,
                      const int*   __restrict__ block_tables,
                      const int*   __restrict__ context_lens,
                      float*       __restrict__ out)
{
    const int split = blockIdx.x;   // fastest-varying: co-schedule a seq's splits
    const int kvh   = blockIdx.y;
    const int seq   = blockIdx.z;
    const int tid   = threadIdx.x;
    const int warp  = tid >> 5;
    const int lane  = tid & 31;

    const int ctx     = context_lens[seq];
    const int nblocks = (ctx + BLOCK_SIZE - 1) / BLOCK_SIZE;
    const int nsplits = (nblocks + BLOCKS_PER_SPLIT - 1) / BLOCKS_PER_SPLIT;
    if (split >= nsplits) return;

    // balanced contiguous range for this split (chunk <= 16 blocks)
    const int bstart = (split * nblocks) / nsplits;
    const int bend   = ((split + 1) * nblocks) / nsplits;

    __shared__ float q_s[Q_PER_KV * HEAD_SIZE];
    __shared__ float w_m[NWARPS][Q_PER_KV];
    __shared__ float w_l[NWARPS][Q_PER_KV];
    __shared__ float w_acc[NWARPS][Q_PER_KV][HEAD_SIZE];
    __shared__ float mg_s[Q_PER_KV];
    __shared__ float den_s[Q_PER_KV];
    __shared__ float f_s[NWARPS][Q_PER_KV];
    __shared__ int   last_s;

    for (int i = tid; i < Q_PER_KV * HEAD_SIZE; i += 256)
        q_s[i] = query[(size_t)(seq * NUM_HEADS + kvh * Q_PER_KV) * HEAD_SIZE + i] * ATTN_SCALE;
    __syncthreads();

    const int blk0 = bstart + warp * 2;
    const int blk1 = blk0 + 1;
    const bool have0 = blk0 < bend;
    const bool have1 = blk1 < bend;

    if (have0) {
        const int pb0 = block_tables[seq * MAX_BLOCKS_PER_SEQ + blk0];
        const int pb1 = have1 ? block_tables[seq * MAX_BLOCKS_PER_SEQ + blk1] : pb0;
        const size_t base0 = ((size_t)pb0 * NUM_KV_HEADS + kvh) * 2048;
        const size_t base1 = ((size_t)pb1 * NUM_KV_HEADS + kvh) * 2048;

        // prefetch both V tiles to L2 while the K phase runs
        {
            const char* v0 = (const char*)(value_cache + base0);
            const char* v1 = (const char*)(value_cache + base1);
            asm volatile("prefetch.global.L2 [%0];" :: "l"(v0 + lane * 128));
            asm volatile("prefetch.global.L2 [%0];" :: "l"(v0 + 4096 + lane * 128));
            asm volatile("prefetch.global.L2 [%0];" :: "l"(v1 + lane * 128));
            asm volatile("prefetch.global.L2 [%0];" :: "l"(v1 + 4096 + lane * 128));
        }

        const int t_lane = lane >> 1;          // token 0..15
        const int dl0    = (lane & 1) * 4;     // 4-dim sub-slot in each 8-dim group

        // ---- K: fully coalesced, all 32 loads in flight (MLP 16/lane, streaming)
        const float4* kb0 = (const float4*)(key_cache + base0);
        const float4* kb1 = (const float4*)(key_cache + base1);

        float s0[Q_PER_KV] = {0.f, 0.f, 0.f, 0.f};
        float s1[Q_PER_KV] = {0.f, 0.f, 0.f, 0.f};

        #pragma unroll
        for (int batch = 0; batch < 2; batch++) {
            float4 kr0[8], kr1[8];
            #pragma unroll
            for (int i = 0; i < 8; i++) {
                const int j = batch * 8 + i;
                kr0[i] = __ldcs(&kb0[j * 32 + lane]);
                kr1[i] = __ldcs(&kb1[j * 32 + lane]);
            }
            #pragma unroll
            for (int i = 0; i < 8; i++) {
                const int j = batch * 8 + i;
                #pragma unroll
                for (int h = 0; h < Q_PER_KV; h++) {
                    const float4 q4 = *(const float4*)(q_s + h * HEAD_SIZE + j * 8 + dl0);
                    s0[h] += q4.x * kr0[i].x + q4.y * kr0[i].y + q4.z * kr0[i].z + q4.w * kr0[i].w;
                    s1[h] += q4.x * kr1[i].x + q4.y * kr1[i].y + q4.z * kr1[i].z + q4.w * kr1[i].w;
                }
            }
        }
        #pragma unroll
        for (int h = 0; h < Q_PER_KV; h++) {
            s0[h] += __shfl_xor_sync(0xffffffffu, s0[h], 1);
            s1[h] += __shfl_xor_sync(0xffffffffu, s1[h], 1);
        }

        const bool valid0 = (blk0 * BLOCK_SIZE + t_lane) < ctx;
        const bool valid1 = have1 && ((blk1 * BLOCK_SIZE + t_lane) < ctx);
        #pragma unroll
        for (int h = 0; h < Q_PER_KV; h++) {
            s0[h] = valid0 ? s0[h] : -1e30f;
            s1[h] = valid1 ? s1[h] : -1e30f;
        }

        // ---- joint softmax over the 32 tokens of both blocks
        float p0[Q_PER_KV], p1[Q_PER_KV];
        #pragma unroll
        for (int h = 0; h < Q_PER_KV; h++) {
            float bm = fmaxf(s0[h], s1[h]);
            #pragma unroll
            for (int off = 2; off < 32; off <<= 1)
                bm = fmaxf(bm, __shfl_xor_sync(0xffffffffu, bm, off));
            p0[h] = __expf(s0[h] - bm);
            p1[h] = __expf(s1[h] - bm);
            float ps = p0[h] + p1[h];
            #pragma unroll
            for (int off = 2; off < 32; off <<= 1)
                ps += __shfl_xor_sync(0xffffffffu, ps, off);
            if (lane == 0) { w_m[warp][h] = bm; w_l[warp][h] = ps; }
        }

        // ---- probs for this lane's 4 tokens (per block)
        float pt0[Q_PER_KV][4], pt1[Q_PER_KV][4];
        const int tok0 = (lane & 3) * 4;
        #pragma unroll
        for (int h = 0; h < Q_PER_KV; h++)
            #pragma unroll
            for (int j = 0; j < 4; j++) {
                pt0[h][j] = __shfl_sync(0xffffffffu, p0[h], (tok0 + j) * 2);
                pt1[h][j] = __shfl_sync(0xffffffffu, p1[h], (tok0 + j) * 2);
            }

        // ---- V: coalesced; lane = (dim 8k + lane/4, tokens tok0..tok0+3)
        const float4* vb0 = (const float4*)(value_cache + base0);
        const float4* vb1 = (const float4*)(value_cache + base1);
        const int dsub = lane >> 2;
        const int gsel = lane & 3;

        #pragma unroll
        for (int kk = 0; kk < 2; kk++) {
            float accv[Q_PER_KV][8];
            #pragma unroll
            for (int j = 0; j < 8; j++) {
                const int k = kk * 8 + j;
                const float4 v0 = __ldcs(&vb0[k * 32 + lane]);
                const float4 v1 = __ldcs(&vb1[k * 32 + lane]);
                #pragma unroll
                for (int h = 0; h < Q_PER_KV; h++)
                    accv[h][j] = v0.x * pt0[h][0] + v0.y * pt0[h][1]
                               + v0.z * pt0[h][2] + v0.w * pt0[h][3]
                               + v1.x * pt1[h][0] + v1.y * pt1[h][1]
                               + v1.z * pt1[h][2] + v1.w * pt1[h][3];
            }
            #pragma unroll
            for (int h = 0; h < Q_PER_KV; h++) {
                #pragma unroll
                for (int j = 0; j < 8; j++) {
                    float v = accv[h][j];
                    v += __shfl_xor_sync(0xffffffffu, v, 1);
                    v += __shfl_xor_sync(0xffffffffu, v, 2);
                    if (gsel == 0)
                        w_acc[warp][h][(kk * 8 + j) * 8 + dsub] = v;
                }
            }
        }
    } else {
        if (lane == 0) {
            #pragma unroll
            for (int h = 0; h < Q_PER_KV; h++) { w_m[warp][h] = -1e30f; w_l[warp][h] = 0.f; }
        }
        const float4 z = make_float4(0.f, 0.f, 0.f, 0.f);
        float4* wa = (float4*)w_acc[warp];     // 128 float4
        #pragma unroll
        for (int r = 0; r < 4; r++) wa[lane + r * 32] = z;
    }
    __syncthreads();

    // ---- CTA merge: per-warp scale factors
    if (tid < Q_PER_KV) {
        float mg = -1e30f;
        #pragma unroll
        for (int w = 0; w < NWARPS; w++) mg = fmaxf(mg, w_m[w][tid]);
        mg_s[tid] = mg;
    }
    __syncthreads();
    if (tid < NWARPS * Q_PER_KV) {
        const int w = tid >> 2;
        const int h = tid & 3;
        f_s[w][h] = __expf(w_m[w][h] - mg_s[h]);
    }
    __syncthreads();
    if (tid < Q_PER_KV) {
        float den = 0.f;
        #pragma unroll
        for (int w = 0; w < NWARPS; w++) den += w_l[w][tid] * f_s[w][tid];
        den_s[tid] = den;
    }
    __syncthreads();

    if (nsplits == 1) {
        // fast path: single split -> write output directly
        for (int o = tid; o < Q_PER_KV * HEAD_SIZE; o += 256) {
            const int h = o >> 7;
            const int d = o & 127;
            float num = 0.f;
            #pragma unroll
            for (int w = 0; w < NWARPS; w++) num += w_acc[w][h][d] * f_s[w][h];
            out[(size_t)(seq * NUM_HEADS + kvh * Q_PER_KV + h) * HEAD_SIZE + d] = num / den_s[h];
        }
        return;
    }

    if (tid < Q_PER_KV) {
        g_ml[seq][kvh][split][tid][0] = mg_s[tid];
        g_ml[seq][kvh][split][tid][1] = den_s[tid];
    }
    for (int o = tid; o < Q_PER_KV * HEAD_SIZE; o += 256) {
        const int h = o >> 7;
        const int d = o & 127;
        float num = 0.f;
        #pragma unroll
        for (int w = 0; w < NWARPS; w++) num += w_acc[w][h][d] * f_s[w][h];
        g_acc[seq][kvh][split][h][d] = num;
    }

    // ---- fused split merge: last-arriving CTA for this (seq,kvh) reduces
    __threadfence();
    __syncthreads();
    if (tid == 0) {
        const unsigned int old = atomicAdd(&g_cnt[seq][kvh], 1u);
        last_s = (old == (unsigned int)(nsplits - 1));
        if (last_s) g_cnt[seq][kvh] = 0u;   // self-reset for next graph replay
    }
    __syncthreads();
    if (!last_s) return;

    for (int o = tid; o < Q_PER_KV * HEAD_SIZE; o += 256) {
        const int h = o >> 7;
        const int d = o & 127;
        float gm = -1e30f;
        #pragma unroll
        for (int s = 0; s < SPLITS; s++)
            if (s < nsplits) gm = fmaxf(gm, g_ml[seq][kvh][s][h][0]);
        float num = 0.f, den = 0.f;
        #pragma unroll
        for (int s = 0; s < SPLITS; s++) {
            if (s < nsplits) {
                const float f = __expf(g_ml[seq][kvh][s][h][0] - gm);
                num += g_acc[seq][kvh][s][h][d] * f;
                den += g_ml[seq][kvh][s][h][1] * f;
            }
        }
        out[(size_t)(seq * NUM_HEADS + kvh * Q_PER_KV + h) * HEAD_SIZE + d] = num / den;
    }
}

extern "C" void kernel_launch(void* const* d_in, const int* in_sizes, int n_in,
                              void* d_out, int out_size)
{
    const float* query       = (const float*)d_in[0];
    const float* key_cache   = (const float*)d_in[1];
    const float* value_cache = (const float*)d_in[2];
    const int*   block_tables  = (const int*)d_in[3];
    const int*   context_lens  = (const int*)d_in[4];
    float* out = (float*)d_out;

    dim3 grid(SPLITS, NUM_KV_HEADS, NUM_SEQS);
    paged_attn_fused<<<grid, 256>>>(query, key_cache, value_cache,
                                    block_tables, context_lens, out);
}